// round 11
// baseline (speedup 1.0000x reference)
#include <cuda_runtime.h>
#include <cub/cub.cuh>

#define B 256
#define M 2048
#define E 128
#define IN_D 512
#define Q_D 512
#define OUT_D 512
#define H 64

// output layout (depth-first flatten of ((wr, nww, nu), output, new_memory))
#define OFF_WR  ((size_t)0)
#define OFF_NWW ((size_t)B*M)
#define OFF_NU  ((size_t)2*B*M)
#define OFF_OUT ((size_t)3*B*M)
#define OFF_NM  ((size_t)3*B*M + (size_t)B*OUT_D)

// scratch (device globals: no allocation allowed)
__device__ float g_emb[B*E];
__device__ float g_avec[B*E];
__device__ float g_bvec[B*E];
__device__ float g_ce[B];
__device__ float g_scores[B*M];
__device__ float g_rbase[B*M];
__device__ float g_alloc[B*M];
__device__ float g_pooled[B*E];

struct MulOp {
    __device__ __forceinline__ float operator()(const float& a, const float& b) const { return a*b; }
};

__device__ __forceinline__ float warp_dot(const float* __restrict__ w,
                                          const float* __restrict__ s,
                                          int n, int lane) {
    float acc = 0.f;
    for (int i = lane; i < n; i += 32) acc += w[i]*s[i];
    #pragma unroll
    for (int o = 16; o > 0; o >>= 1) acc += __shfl_down_sync(0xffffffffu, acc, o);
    return acc;  // valid on lane 0
}

// ---------------------------------------------------------------------------
// Kernel 0: per-batch small GEMMs -> g_emb, g_avec, g_bvec, g_ce; zero pooled.
// ---------------------------------------------------------------------------
__global__ void k_pre(const float* __restrict__ x, const float* __restrict__ query,
                      const float* __restrict__ Iw, const float* __restrict__ Ib,
                      const float* __restrict__ W1w, const float* __restrict__ W1b,
                      const float* __restrict__ W2w,
                      const float* __restrict__ R1w, const float* __restrict__ R1b,
                      const float* __restrict__ R2w) {
    int b = blockIdx.x, t = threadIdx.x;      // 128 threads, 4 warps
    int lane = t & 31, wid = t >> 5;
    __shared__ float sx[IN_D], sq[Q_D], semb[E], sWi[H], sRq[H], sred[E];
    for (int i = t; i < IN_D; i += 128) sx[i] = x[(size_t)b*IN_D + i];
    for (int i = t; i < Q_D;  i += 128) sq[i] = query[(size_t)b*Q_D + i];
    if (t < E) g_pooled[(size_t)b*E + t] = 0.f;
    __syncthreads();
    for (int o = wid; o < E; o += 4) {
        float d = warp_dot(Iw + (size_t)o*IN_D, sx, IN_D, lane);
        if (lane == 0) { d += Ib[o]; semb[o] = d; g_emb[(size_t)b*E + o] = d; }
    }
    __syncthreads();
    for (int o = wid; o < H; o += 4) {
        float d = warp_dot(W1w + (size_t)o*E, semb, E, lane);
        if (lane == 0) sWi[o] = d + W1b[o];
        float d2 = warp_dot(R1w + (size_t)o*Q_D, sq, Q_D, lane);
        if (lane == 0) sRq[o] = d2 + R1b[o];
    }
    __syncthreads();
    {
        float av = 0.f, bv = 0.f;
        #pragma unroll 8
        for (int h = 0; h < H; h++) {
            av += sWi[h]*W2w[(size_t)h*E + t];
            bv += sRq[h]*R2w[(size_t)h*E + t];
        }
        g_avec[(size_t)b*E + t] = av;
        g_bvec[(size_t)b*E + t] = bv;
        sred[t] = bv*semb[t];
    }
    __syncthreads();
    for (int s = 64; s > 0; s >>= 1) { if (t < s) sred[t] += sred[t+s]; __syncthreads(); }
    if (t == 0) g_ce[b] = sred[0];
}

// ---------------------------------------------------------------------------
// Role-split kernel, 256 threads/block:
//   blocks [0,256):      sort role — usage update, radix argsort (24 bits,
//                        4 passes of 6 bits), cumprod scan, alloc -> g_alloc
//   blocks [256,16640):  dots role — stream memory, scores/rbase dots
// Sort depends ONLY on rw/ww/us/fg; 256-thr blocks give ~4 sort blocks/SM
// (vs 2 at 512 thr) so barrier/smem latency chains are better hidden, and
// RADIX_BITS=6 cuts passes 6 -> 4 at identical 24-bit stable numerics.
// ---------------------------------------------------------------------------
__global__ void __launch_bounds__(256) k_dotsort(const float* __restrict__ mem,
        const float* __restrict__ rw, const float* __restrict__ ww,
        const float* __restrict__ us, const float* __restrict__ fg,
        float* __restrict__ out) {
    typedef cub::BlockRadixSort<unsigned int, 256, 8, unsigned int, 6> Sorter;
    typedef cub::BlockScan<float, 256> Scanner;
    __shared__ union SU {
        typename Sorter::TempStorage  sort;
        typename Scanner::TempStorage scan;
        struct { float sa[E]; float sb[E]; } d;
    } sm;

    int t = threadIdx.x;
    if (blockIdx.x < B) {
        // -------- sort role --------
        int b = blockIdx.x;
        size_t base = (size_t)b*M;
        unsigned int keys[8], vals[8];
        {
            float4 U0  = ((const float4*)(us + base))[2*t],   U1  = ((const float4*)(us + base))[2*t+1];
            float4 W0  = ((const float4*)(ww + base))[2*t],   W1  = ((const float4*)(ww + base))[2*t+1];
            float4 F0  = ((const float4*)(fg + base))[2*t],   F1  = ((const float4*)(fg + base))[2*t+1];
            float4 R0  = ((const float4*)(rw + base))[2*t],   R1  = ((const float4*)(rw + base))[2*t+1];
            float uu[8] = {U0.x,U0.y,U0.z,U0.w, U1.x,U1.y,U1.z,U1.w};
            float wv[8] = {W0.x,W0.y,W0.z,W0.w, W1.x,W1.y,W1.z,W1.w};
            float ff[8] = {F0.x,F0.y,F0.z,F0.w, F1.x,F1.y,F1.z,F1.w};
            float rr[8] = {R0.x,R0.y,R0.z,R0.w, R1.x,R1.y,R1.z,R1.w};
            #pragma unroll
            for (int i = 0; i < 8; i++) {
                float u = 1e-5f + (1.f - 1e-5f)*uu[i];
                u = u + wv[i] - u*wv[i];
                u *= (1.f - ff[i]*rr[i]);
                keys[i] = __float_as_uint(u);
                vals[i] = 8*t + i;
            }
            ((float4*)(out + OFF_NU + base))[2*t] =
                make_float4(__uint_as_float(keys[0]), __uint_as_float(keys[1]),
                            __uint_as_float(keys[2]), __uint_as_float(keys[3]));
            ((float4*)(out + OFF_NU + base))[2*t+1] =
                make_float4(__uint_as_float(keys[4]), __uint_as_float(keys[5]),
                            __uint_as_float(keys[6]), __uint_as_float(keys[7]));
        }
        __syncthreads();
        // top 24 bits: u>0 so uint order == float order; stable radix -> tie
        // order matches jnp.argsort; quantized-tie mis-order perturbs alloc
        // by <2^-15 rel (measured-passing config, unchanged)
        Sorter(sm.sort).Sort(keys, vals, 8, 32);
        __syncthreads();
        float su[8], cp[8];
        #pragma unroll
        for (int i = 0; i < 8; i++) su[i] = __uint_as_float(keys[i]);
        Scanner(sm.scan).InclusiveScan(su, cp, MulOp());
        #pragma unroll
        for (int i = 0; i < 8; i++)
            g_alloc[base + vals[i]] = (1.f - su[i])*cp[i];
    } else {
        // -------- dots role --------
        int idx = blockIdx.x - B;
        int b = idx >> 6;            // 64 blocks per batch
        int chunk = idx & 63;
        int warp = t >> 5, lane = t & 31;   // 8 warps
        if (t < E) {
            sm.d.sa[t] = g_avec[(size_t)b*E + t];
            sm.d.sb[t] = g_bvec[(size_t)b*E + t];
        }
        __syncthreads();
        int m0 = chunk*32 + warp*4;
        const float4* mrow = (const float4*)(mem + (size_t)b*M*E);
        float4 v[4];
        #pragma unroll
        for (int k = 0; k < 4; k++)
            v[k] = mrow[(size_t)(m0 + k)*32 + lane];
        float4 a  = ((const float4*)sm.d.sa)[lane];
        float4 bb = ((const float4*)sm.d.sb)[lane];
        float ds[4], dr[4];
        #pragma unroll
        for (int k = 0; k < 4; k++) {
            ds[k] = v[k].x*a.x + v[k].y*a.y + v[k].z*a.z + v[k].w*a.w;
            dr[k] = v[k].x*bb.x + v[k].y*bb.y + v[k].z*bb.z + v[k].w*bb.w;
        }
        #pragma unroll
        for (int o = 16; o > 0; o >>= 1) {
            #pragma unroll
            for (int k = 0; k < 4; k++) {
                ds[k] += __shfl_down_sync(0xffffffffu, ds[k], o);
                dr[k] += __shfl_down_sync(0xffffffffu, dr[k], o);
            }
        }
        if (lane == 0) {
            #pragma unroll
            for (int k = 0; k < 4; k++) {
                g_scores[(size_t)b*M + m0 + k] = ds[k];
                g_rbase [(size_t)b*M + m0 + k] = dr[k];
            }
        }
    }
}

// ---------------------------------------------------------------------------
// Per-batch softmax tail: w = 0.5*(softmax(scores)+alloc);
// wr = softmax(rbase + w*ce).
// ---------------------------------------------------------------------------
__global__ void __launch_bounds__(512) k_wsoft(float* __restrict__ out) {
    int b = blockIdx.x, t = threadIdx.x;
    int lane = t & 31, wid = t >> 5;
    size_t base = (size_t)b*M;
    __shared__ float sred[16];
    __shared__ float bc;

    float4 sc = ((const float4*)(g_scores + base))[t];
    float v = fmaxf(fmaxf(sc.x, sc.y), fmaxf(sc.z, sc.w));
    #pragma unroll
    for (int o = 16; o > 0; o >>= 1) v = fmaxf(v, __shfl_xor_sync(0xffffffffu, v, o));
    if (lane == 0) sred[wid] = v;
    __syncthreads();
    if (t < 16) {
        float xx = sred[t];
        #pragma unroll
        for (int o = 8; o > 0; o >>= 1) xx = fmaxf(xx, __shfl_xor_sync(0xffffu, xx, o));
        if (t == 0) bc = xx;
    }
    __syncthreads();
    float mx = bc;
    float e0 = __expf(sc.x - mx), e1 = __expf(sc.y - mx);
    float e2 = __expf(sc.z - mx), e3 = __expf(sc.w - mx);
    v = (e0 + e1) + (e2 + e3);
    #pragma unroll
    for (int o = 16; o > 0; o >>= 1) v += __shfl_xor_sync(0xffffffffu, v, o);
    if (lane == 0) sred[wid] = v;
    __syncthreads();
    if (t < 16) {
        float xx = sred[t];
        #pragma unroll
        for (int o = 8; o > 0; o >>= 1) xx += __shfl_xor_sync(0xffffu, xx, o);
        if (t == 0) bc = xx;
    }
    __syncthreads();
    float inv = 1.f/bc;
    float4 al = ((const float4*)(g_alloc + base))[t];
    float w0 = 0.5f*(e0*inv + al.x);
    float w1 = 0.5f*(e1*inv + al.y);
    float w2 = 0.5f*(e2*inv + al.z);
    float w3 = 0.5f*(e3*inv + al.w);
    ((float4*)(out + OFF_NWW + base))[t] = make_float4(w0, w1, w2, w3);
    __syncthreads();   // bc reuse guard

    float ce = g_ce[b];
    float4 rb = ((const float4*)(g_rbase + base))[t];
    float r0 = rb.x + w0*ce, r1 = rb.y + w1*ce;
    float r2 = rb.z + w2*ce, r3 = rb.w + w3*ce;
    v = fmaxf(fmaxf(r0, r1), fmaxf(r2, r3));
    #pragma unroll
    for (int o = 16; o > 0; o >>= 1) v = fmaxf(v, __shfl_xor_sync(0xffffffffu, v, o));
    if (lane == 0) sred[wid] = v;
    __syncthreads();
    if (t < 16) {
        float xx = sred[t];
        #pragma unroll
        for (int o = 8; o > 0; o >>= 1) xx = fmaxf(xx, __shfl_xor_sync(0xffffu, xx, o));
        if (t == 0) bc = xx;
    }
    __syncthreads();
    mx = bc;
    e0 = __expf(r0 - mx); e1 = __expf(r1 - mx);
    e2 = __expf(r2 - mx); e3 = __expf(r3 - mx);
    v = (e0 + e1) + (e2 + e3);
    #pragma unroll
    for (int o = 16; o > 0; o >>= 1) v += __shfl_xor_sync(0xffffffffu, v, o);
    if (lane == 0) sred[wid] = v;
    __syncthreads();
    if (t < 16) {
        float xx = sred[t];
        #pragma unroll
        for (int o = 8; o > 0; o >>= 1) xx += __shfl_xor_sync(0xffffu, xx, o);
        if (t == 0) bc = xx;
    }
    __syncthreads();
    inv = 1.f/bc;
    ((float4*)(out + OFF_WR + base))[t] = make_float4(e0*inv, e1*inv, e2*inv, e3*inv);
}

// ---------------------------------------------------------------------------
// Pass B: new_mem = mem + w*emb (write), pooled += wr*new_mem.
// Batches iterated in REVERSE so the tail of `mem` (still L2-resident from
// the dots pass) is consumed before it gets evicted.
// ---------------------------------------------------------------------------
__global__ void k_passB(const float* __restrict__ mem, float* __restrict__ out) {
    int b = B - 1 - blockIdx.y;
    int warp = threadIdx.x >> 5, lane = threadIdx.x & 31;
    __shared__ __align__(16) float semb[E];
    __shared__ float spool[E];
    if (threadIdx.x < E) {
        semb[threadIdx.x] = g_emb[(size_t)b*E + threadIdx.x];
        spool[threadIdx.x] = 0.f;
    }
    __syncthreads();
    float4 em = ((const float4*)semb)[lane];
    const float* wptr  = out + OFF_NWW + (size_t)b*M;
    const float* wrptr = out + OFF_WR  + (size_t)b*M;
    float4 p = make_float4(0.f, 0.f, 0.f, 0.f);
    int mbase = blockIdx.x*128 + warp*16;
    #pragma unroll 4
    for (int r = 0; r < 16; r++) {
        int m = mbase + r;
        float wv  = wptr[m];
        float wrv = wrptr[m];
        const float4* row = (const float4*)(mem + ((size_t)b*M + m)*E);
        float4 v = row[lane];
        float4 nm;
        nm.x = v.x + wv*em.x; nm.y = v.y + wv*em.y;
        nm.z = v.z + wv*em.z; nm.w = v.w + wv*em.w;
        ((float4*)(out + OFF_NM + ((size_t)b*M + m)*E))[lane] = nm;
        p.x += wrv*nm.x; p.y += wrv*nm.y; p.z += wrv*nm.z; p.w += wrv*nm.w;
    }
    atomicAdd(&spool[lane*4+0], p.x);
    atomicAdd(&spool[lane*4+1], p.y);
    atomicAdd(&spool[lane*4+2], p.z);
    atomicAdd(&spool[lane*4+3], p.w);
    __syncthreads();
    if (threadIdx.x < E)
        atomicAdd(&g_pooled[(size_t)b*E + threadIdx.x], spool[threadIdx.x]);
}

// ---------------------------------------------------------------------------
// Output projection: grid (8, B), warp per output row, 8 rows per warp.
// ---------------------------------------------------------------------------
__global__ void k_out(const float* __restrict__ Ow, const float* __restrict__ Ob,
                      float* __restrict__ out) {
    int b = blockIdx.y, chunk = blockIdx.x;
    int lane = threadIdx.x & 31, wid = threadIdx.x >> 5;   // 8 warps
    __shared__ __align__(16) float sp[E];
    if (threadIdx.x < E) sp[threadIdx.x] = g_pooled[(size_t)b*E + threadIdx.x];
    __syncthreads();
    float4 pv = ((const float4*)sp)[lane];
    int o0 = chunk*64 + wid*8;
    float d[8];
    #pragma unroll
    for (int r = 0; r < 8; r++) {
        float4 wv = ((const float4*)(Ow + (size_t)(o0 + r)*E))[lane];
        d[r] = wv.x*pv.x + wv.y*pv.y + wv.z*pv.z + wv.w*pv.w;
    }
    #pragma unroll
    for (int o = 16; o > 0; o >>= 1) {
        #pragma unroll
        for (int r = 0; r < 8; r++)
            d[r] += __shfl_down_sync(0xffffffffu, d[r], o);
    }
    if (lane == 0) {
        #pragma unroll
        for (int r = 0; r < 8; r++)
            out[OFF_OUT + (size_t)b*OUT_D + o0 + r] = d[r] + Ob[o0 + r];
    }
}

extern "C" void kernel_launch(void* const* d_in, const int* in_sizes, int n_in,
                              void* d_out, int out_size) {
    const float* rw  = (const float*)d_in[0];
    const float* ww  = (const float*)d_in[1];
    const float* us  = (const float*)d_in[2];
    const float* fg  = (const float*)d_in[3];
    const float* x   = (const float*)d_in[4];
    const float* q   = (const float*)d_in[5];
    const float* mem = (const float*)d_in[6];
    const float* Iw  = (const float*)d_in[7];
    const float* Ib  = (const float*)d_in[8];
    const float* W1w = (const float*)d_in[9];
    const float* W1b = (const float*)d_in[10];
    const float* W2w = (const float*)d_in[11];
    // d_in[12] = W2_b: per-batch constant, cancels in softmax
    const float* R1w = (const float*)d_in[13];
    const float* R1b = (const float*)d_in[14];
    const float* R2w = (const float*)d_in[15];
    // d_in[16] = R2_b: per-batch constant, cancels in softmax
    const float* Ow  = (const float*)d_in[17];
    const float* Ob  = (const float*)d_in[18];
    float* out = (float*)d_out;

    k_pre    <<<B, 128>>>(x, q, Iw, Ib, W1w, W1b, W2w, R1w, R1b, R2w);
    k_dotsort<<<B + B*64, 256>>>(mem, rw, ww, us, fg, out);
    k_wsoft  <<<B, 512>>>(out);
    k_passB  <<<dim3(M/128, B), 256>>>(mem, out);
    k_out    <<<dim3(8, B), 256>>>(Ow, Ob, out);
}

// round 12
// speedup vs baseline: 1.0027x; 1.0027x over previous
#include <cuda_runtime.h>
#include <cub/cub.cuh>

#define B 256
#define M 2048
#define E 128
#define IN_D 512
#define Q_D 512
#define OUT_D 512
#define H 64

// output layout (depth-first flatten of ((wr, nww, nu), output, new_memory))
#define OFF_WR  ((size_t)0)
#define OFF_NWW ((size_t)B*M)
#define OFF_NU  ((size_t)2*B*M)
#define OFF_OUT ((size_t)3*B*M)
#define OFF_NM  ((size_t)3*B*M + (size_t)B*OUT_D)

// scratch (device globals: no allocation allowed)
__device__ float g_emb[B*E];
__device__ float g_avec[B*E];
__device__ float g_bvec[B*E];
__device__ float g_ce[B];
__device__ float g_scores[B*M];
__device__ float g_rbase[B*M];
__device__ float g_alloc[B*M];
__device__ float g_pooled[B*E];

struct MulOp {
    __device__ __forceinline__ float operator()(const float& a, const float& b) const { return a*b; }
};

__device__ __forceinline__ float warp_dot(const float* __restrict__ w,
                                          const float* __restrict__ s,
                                          int n, int lane) {
    float acc = 0.f;
    for (int i = lane; i < n; i += 32) acc += w[i]*s[i];
    #pragma unroll
    for (int o = 16; o > 0; o >>= 1) acc += __shfl_down_sync(0xffffffffu, acc, o);
    return acc;  // valid on lane 0
}

// ---------------------------------------------------------------------------
// Kernel 0: per-batch small GEMMs -> g_emb, g_avec, g_bvec, g_ce; zero pooled.
// ---------------------------------------------------------------------------
__global__ void k_pre(const float* __restrict__ x, const float* __restrict__ query,
                      const float* __restrict__ Iw, const float* __restrict__ Ib,
                      const float* __restrict__ W1w, const float* __restrict__ W1b,
                      const float* __restrict__ W2w,
                      const float* __restrict__ R1w, const float* __restrict__ R1b,
                      const float* __restrict__ R2w) {
    int b = blockIdx.x, t = threadIdx.x;      // 128 threads, 4 warps
    int lane = t & 31, wid = t >> 5;
    __shared__ float sx[IN_D], sq[Q_D], semb[E], sWi[H], sRq[H], sred[E];
    for (int i = t; i < IN_D; i += 128) sx[i] = x[(size_t)b*IN_D + i];
    for (int i = t; i < Q_D;  i += 128) sq[i] = query[(size_t)b*Q_D + i];
    if (t < E) g_pooled[(size_t)b*E + t] = 0.f;
    __syncthreads();
    for (int o = wid; o < E; o += 4) {
        float d = warp_dot(Iw + (size_t)o*IN_D, sx, IN_D, lane);
        if (lane == 0) { d += Ib[o]; semb[o] = d; g_emb[(size_t)b*E + o] = d; }
    }
    __syncthreads();
    for (int o = wid; o < H; o += 4) {
        float d = warp_dot(W1w + (size_t)o*E, semb, E, lane);
        if (lane == 0) sWi[o] = d + W1b[o];
        float d2 = warp_dot(R1w + (size_t)o*Q_D, sq, Q_D, lane);
        if (lane == 0) sRq[o] = d2 + R1b[o];
    }
    __syncthreads();
    {
        float av = 0.f, bv = 0.f;
        #pragma unroll 8
        for (int h = 0; h < H; h++) {
            av += sWi[h]*W2w[(size_t)h*E + t];
            bv += sRq[h]*R2w[(size_t)h*E + t];
        }
        g_avec[(size_t)b*E + t] = av;
        g_bvec[(size_t)b*E + t] = bv;
        sred[t] = bv*semb[t];
    }
    __syncthreads();
    for (int s = 64; s > 0; s >>= 1) { if (t < s) sred[t] += sred[t+s]; __syncthreads(); }
    if (t == 0) g_ce[b] = sred[0];
}

// ---------------------------------------------------------------------------
// Role-split kernel, 256 threads/block:
//   blocks [0,256):      sort role — usage update, radix argsort (24 bits,
//                        4 passes of 6 bits), cumprod scan, alloc -> g_alloc
//   blocks [256,16640):  dots role — stream memory, scores/rbase dots
// Sort depends ONLY on rw/ww/us/fg; 256-thr blocks give ~4 sort blocks/SM
// (vs 2 at 512 thr) so barrier/smem latency chains are better hidden, and
// RADIX_BITS=6 cuts passes 6 -> 4 at identical 24-bit stable numerics.
// ---------------------------------------------------------------------------
__global__ void __launch_bounds__(256) k_dotsort(const float* __restrict__ mem,
        const float* __restrict__ rw, const float* __restrict__ ww,
        const float* __restrict__ us, const float* __restrict__ fg,
        float* __restrict__ out) {
    typedef cub::BlockRadixSort<unsigned int, 256, 8, unsigned int, 6> Sorter;
    typedef cub::BlockScan<float, 256> Scanner;
    __shared__ union SU {
        typename Sorter::TempStorage  sort;
        typename Scanner::TempStorage scan;
        struct { float sa[E]; float sb[E]; } d;
    } sm;

    int t = threadIdx.x;
    if (blockIdx.x < B) {
        // -------- sort role --------
        int b = blockIdx.x;
        size_t base = (size_t)b*M;
        unsigned int keys[8], vals[8];
        {
            float4 U0  = ((const float4*)(us + base))[2*t],   U1  = ((const float4*)(us + base))[2*t+1];
            float4 W0  = ((const float4*)(ww + base))[2*t],   W1  = ((const float4*)(ww + base))[2*t+1];
            float4 F0  = ((const float4*)(fg + base))[2*t],   F1  = ((const float4*)(fg + base))[2*t+1];
            float4 R0  = ((const float4*)(rw + base))[2*t],   R1  = ((const float4*)(rw + base))[2*t+1];
            float uu[8] = {U0.x,U0.y,U0.z,U0.w, U1.x,U1.y,U1.z,U1.w};
            float wv[8] = {W0.x,W0.y,W0.z,W0.w, W1.x,W1.y,W1.z,W1.w};
            float ff[8] = {F0.x,F0.y,F0.z,F0.w, F1.x,F1.y,F1.z,F1.w};
            float rr[8] = {R0.x,R0.y,R0.z,R0.w, R1.x,R1.y,R1.z,R1.w};
            #pragma unroll
            for (int i = 0; i < 8; i++) {
                float u = 1e-5f + (1.f - 1e-5f)*uu[i];
                u = u + wv[i] - u*wv[i];
                u *= (1.f - ff[i]*rr[i]);
                keys[i] = __float_as_uint(u);
                vals[i] = 8*t + i;
            }
            ((float4*)(out + OFF_NU + base))[2*t] =
                make_float4(__uint_as_float(keys[0]), __uint_as_float(keys[1]),
                            __uint_as_float(keys[2]), __uint_as_float(keys[3]));
            ((float4*)(out + OFF_NU + base))[2*t+1] =
                make_float4(__uint_as_float(keys[4]), __uint_as_float(keys[5]),
                            __uint_as_float(keys[6]), __uint_as_float(keys[7]));
        }
        __syncthreads();
        // top 24 bits: u>0 so uint order == float order; stable radix -> tie
        // order matches jnp.argsort; quantized-tie mis-order perturbs alloc
        // by <2^-15 rel (measured-passing config, unchanged)
        Sorter(sm.sort).Sort(keys, vals, 8, 32);
        __syncthreads();
        float su[8], cp[8];
        #pragma unroll
        for (int i = 0; i < 8; i++) su[i] = __uint_as_float(keys[i]);
        Scanner(sm.scan).InclusiveScan(su, cp, MulOp());
        #pragma unroll
        for (int i = 0; i < 8; i++)
            g_alloc[base + vals[i]] = (1.f - su[i])*cp[i];
    } else {
        // -------- dots role --------
        int idx = blockIdx.x - B;
        int b = idx >> 6;            // 64 blocks per batch
        int chunk = idx & 63;
        int warp = t >> 5, lane = t & 31;   // 8 warps
        if (t < E) {
            sm.d.sa[t] = g_avec[(size_t)b*E + t];
            sm.d.sb[t] = g_bvec[(size_t)b*E + t];
        }
        __syncthreads();
        int m0 = chunk*32 + warp*4;
        const float4* mrow = (const float4*)(mem + (size_t)b*M*E);
        float4 v[4];
        #pragma unroll
        for (int k = 0; k < 4; k++)
            v[k] = mrow[(size_t)(m0 + k)*32 + lane];
        float4 a  = ((const float4*)sm.d.sa)[lane];
        float4 bb = ((const float4*)sm.d.sb)[lane];
        float ds[4], dr[4];
        #pragma unroll
        for (int k = 0; k < 4; k++) {
            ds[k] = v[k].x*a.x + v[k].y*a.y + v[k].z*a.z + v[k].w*a.w;
            dr[k] = v[k].x*bb.x + v[k].y*bb.y + v[k].z*bb.z + v[k].w*bb.w;
        }
        #pragma unroll
        for (int o = 16; o > 0; o >>= 1) {
            #pragma unroll
            for (int k = 0; k < 4; k++) {
                ds[k] += __shfl_down_sync(0xffffffffu, ds[k], o);
                dr[k] += __shfl_down_sync(0xffffffffu, dr[k], o);
            }
        }
        if (lane == 0) {
            #pragma unroll
            for (int k = 0; k < 4; k++) {
                g_scores[(size_t)b*M + m0 + k] = ds[k];
                g_rbase [(size_t)b*M + m0 + k] = dr[k];
            }
        }
    }
}

// ---------------------------------------------------------------------------
// Per-batch softmax tail: w = 0.5*(softmax(scores)+alloc);
// wr = softmax(rbase + w*ce).
// ---------------------------------------------------------------------------
__global__ void __launch_bounds__(512) k_wsoft(float* __restrict__ out) {
    int b = blockIdx.x, t = threadIdx.x;
    int lane = t & 31, wid = t >> 5;
    size_t base = (size_t)b*M;
    __shared__ float sred[16];
    __shared__ float bc;

    float4 sc = ((const float4*)(g_scores + base))[t];
    float v = fmaxf(fmaxf(sc.x, sc.y), fmaxf(sc.z, sc.w));
    #pragma unroll
    for (int o = 16; o > 0; o >>= 1) v = fmaxf(v, __shfl_xor_sync(0xffffffffu, v, o));
    if (lane == 0) sred[wid] = v;
    __syncthreads();
    if (t < 16) {
        float xx = sred[t];
        #pragma unroll
        for (int o = 8; o > 0; o >>= 1) xx = fmaxf(xx, __shfl_xor_sync(0xffffu, xx, o));
        if (t == 0) bc = xx;
    }
    __syncthreads();
    float mx = bc;
    float e0 = __expf(sc.x - mx), e1 = __expf(sc.y - mx);
    float e2 = __expf(sc.z - mx), e3 = __expf(sc.w - mx);
    v = (e0 + e1) + (e2 + e3);
    #pragma unroll
    for (int o = 16; o > 0; o >>= 1) v += __shfl_xor_sync(0xffffffffu, v, o);
    if (lane == 0) sred[wid] = v;
    __syncthreads();
    if (t < 16) {
        float xx = sred[t];
        #pragma unroll
        for (int o = 8; o > 0; o >>= 1) xx += __shfl_xor_sync(0xffffu, xx, o);
        if (t == 0) bc = xx;
    }
    __syncthreads();
    float inv = 1.f/bc;
    float4 al = ((const float4*)(g_alloc + base))[t];
    float w0 = 0.5f*(e0*inv + al.x);
    float w1 = 0.5f*(e1*inv + al.y);
    float w2 = 0.5f*(e2*inv + al.z);
    float w3 = 0.5f*(e3*inv + al.w);
    ((float4*)(out + OFF_NWW + base))[t] = make_float4(w0, w1, w2, w3);
    __syncthreads();   // bc reuse guard

    float ce = g_ce[b];
    float4 rb = ((const float4*)(g_rbase + base))[t];
    float r0 = rb.x + w0*ce, r1 = rb.y + w1*ce;
    float r2 = rb.z + w2*ce, r3 = rb.w + w3*ce;
    v = fmaxf(fmaxf(r0, r1), fmaxf(r2, r3));
    #pragma unroll
    for (int o = 16; o > 0; o >>= 1) v = fmaxf(v, __shfl_xor_sync(0xffffffffu, v, o));
    if (lane == 0) sred[wid] = v;
    __syncthreads();
    if (t < 16) {
        float xx = sred[t];
        #pragma unroll
        for (int o = 8; o > 0; o >>= 1) xx = fmaxf(xx, __shfl_xor_sync(0xffffu, xx, o));
        if (t == 0) bc = xx;
    }
    __syncthreads();
    mx = bc;
    e0 = __expf(r0 - mx); e1 = __expf(r1 - mx);
    e2 = __expf(r2 - mx); e3 = __expf(r3 - mx);
    v = (e0 + e1) + (e2 + e3);
    #pragma unroll
    for (int o = 16; o > 0; o >>= 1) v += __shfl_xor_sync(0xffffffffu, v, o);
    if (lane == 0) sred[wid] = v;
    __syncthreads();
    if (t < 16) {
        float xx = sred[t];
        #pragma unroll
        for (int o = 8; o > 0; o >>= 1) xx += __shfl_xor_sync(0xffffu, xx, o);
        if (t == 0) bc = xx;
    }
    __syncthreads();
    inv = 1.f/bc;
    ((float4*)(out + OFF_WR + base))[t] = make_float4(e0*inv, e1*inv, e2*inv, e3*inv);
}

// ---------------------------------------------------------------------------
// Pass B: new_mem = mem + w*emb (write), pooled += wr*new_mem.
// Batches iterated in REVERSE so the tail of `mem` (still L2-resident from
// the dots pass) is consumed before it gets evicted.
// ---------------------------------------------------------------------------
__global__ void k_passB(const float* __restrict__ mem, float* __restrict__ out) {
    int b = B - 1 - blockIdx.y;
    int warp = threadIdx.x >> 5, lane = threadIdx.x & 31;
    __shared__ __align__(16) float semb[E];
    __shared__ float spool[E];
    if (threadIdx.x < E) {
        semb[threadIdx.x] = g_emb[(size_t)b*E + threadIdx.x];
        spool[threadIdx.x] = 0.f;
    }
    __syncthreads();
    float4 em = ((const float4*)semb)[lane];
    const float* wptr  = out + OFF_NWW + (size_t)b*M;
    const float* wrptr = out + OFF_WR  + (size_t)b*M;
    float4 p = make_float4(0.f, 0.f, 0.f, 0.f);
    int mbase = blockIdx.x*128 + warp*16;
    #pragma unroll 4
    for (int r = 0; r < 16; r++) {
        int m = mbase + r;
        float wv  = wptr[m];
        float wrv = wrptr[m];
        const float4* row = (const float4*)(mem + ((size_t)b*M + m)*E);
        float4 v = row[lane];
        float4 nm;
        nm.x = v.x + wv*em.x; nm.y = v.y + wv*em.y;
        nm.z = v.z + wv*em.z; nm.w = v.w + wv*em.w;
        ((float4*)(out + OFF_NM + ((size_t)b*M + m)*E))[lane] = nm;
        p.x += wrv*nm.x; p.y += wrv*nm.y; p.z += wrv*nm.z; p.w += wrv*nm.w;
    }
    atomicAdd(&spool[lane*4+0], p.x);
    atomicAdd(&spool[lane*4+1], p.y);
    atomicAdd(&spool[lane*4+2], p.z);
    atomicAdd(&spool[lane*4+3], p.w);
    __syncthreads();
    if (threadIdx.x < E)
        atomicAdd(&g_pooled[(size_t)b*E + threadIdx.x], spool[threadIdx.x]);
}

// ---------------------------------------------------------------------------
// Output projection: grid (8, B), warp per output row, 8 rows per warp.
// ---------------------------------------------------------------------------
__global__ void k_out(const float* __restrict__ Ow, const float* __restrict__ Ob,
                      float* __restrict__ out) {
    int b = blockIdx.y, chunk = blockIdx.x;
    int lane = threadIdx.x & 31, wid = threadIdx.x >> 5;   // 8 warps
    __shared__ __align__(16) float sp[E];
    if (threadIdx.x < E) sp[threadIdx.x] = g_pooled[(size_t)b*E + threadIdx.x];
    __syncthreads();
    float4 pv = ((const float4*)sp)[lane];
    int o0 = chunk*64 + wid*8;
    float d[8];
    #pragma unroll
    for (int r = 0; r < 8; r++) {
        float4 wv = ((const float4*)(Ow + (size_t)(o0 + r)*E))[lane];
        d[r] = wv.x*pv.x + wv.y*pv.y + wv.z*pv.z + wv.w*pv.w;
    }
    #pragma unroll
    for (int o = 16; o > 0; o >>= 1) {
        #pragma unroll
        for (int r = 0; r < 8; r++)
            d[r] += __shfl_down_sync(0xffffffffu, d[r], o);
    }
    if (lane == 0) {
        #pragma unroll
        for (int r = 0; r < 8; r++)
            out[OFF_OUT + (size_t)b*OUT_D + o0 + r] = d[r] + Ob[o0 + r];
    }
}

extern "C" void kernel_launch(void* const* d_in, const int* in_sizes, int n_in,
                              void* d_out, int out_size) {
    const float* rw  = (const float*)d_in[0];
    const float* ww  = (const float*)d_in[1];
    const float* us  = (const float*)d_in[2];
    const float* fg  = (const float*)d_in[3];
    const float* x   = (const float*)d_in[4];
    const float* q   = (const float*)d_in[5];
    const float* mem = (const float*)d_in[6];
    const float* Iw  = (const float*)d_in[7];
    const float* Ib  = (const float*)d_in[8];
    const float* W1w = (const float*)d_in[9];
    const float* W1b = (const float*)d_in[10];
    const float* W2w = (const float*)d_in[11];
    // d_in[12] = W2_b: per-batch constant, cancels in softmax
    const float* R1w = (const float*)d_in[13];
    const float* R1b = (const float*)d_in[14];
    const float* R2w = (const float*)d_in[15];
    // d_in[16] = R2_b: per-batch constant, cancels in softmax
    const float* Ow  = (const float*)d_in[17];
    const float* Ob  = (const float*)d_in[18];
    float* out = (float*)d_out;

    k_pre    <<<B, 128>>>(x, q, Iw, Ib, W1w, W1b, W2w, R1w, R1b, R2w);
    k_dotsort<<<B + B*64, 256>>>(mem, rw, ww, us, fg, out);
    k_wsoft  <<<B, 512>>>(out);
    k_passB  <<<dim3(M/128, B), 256>>>(mem, out);
    k_out    <<<dim3(8, B), 256>>>(Ow, Ob, out);
}

// round 13
// speedup vs baseline: 1.0261x; 1.0233x over previous
#include <cuda_runtime.h>
#include <cub/cub.cuh>

#define B 256
#define M 2048
#define E 128
#define IN_D 512
#define Q_D 512
#define OUT_D 512
#define H 64

// output layout (depth-first flatten of ((wr, nww, nu), output, new_memory))
#define OFF_WR  ((size_t)0)
#define OFF_NWW ((size_t)B*M)
#define OFF_NU  ((size_t)2*B*M)
#define OFF_OUT ((size_t)3*B*M)
#define OFF_NM  ((size_t)3*B*M + (size_t)B*OUT_D)

// scratch (device globals: no allocation allowed)
__device__ float g_emb[B*E];
__device__ float g_avec[B*E];
__device__ float g_bvec[B*E];
__device__ float g_ce[B];
__device__ float g_scores[B*M];
__device__ float g_rbase[B*M];
__device__ float g_pooled[B*E];

struct MulOp {
    __device__ __forceinline__ float operator()(const float& a, const float& b) const { return a*b; }
};

__device__ __forceinline__ float warp_dot(const float* __restrict__ w,
                                          const float* __restrict__ s,
                                          int n, int lane) {
    float acc = 0.f;
    for (int i = lane; i < n; i += 32) acc += w[i]*s[i];
    #pragma unroll
    for (int o = 16; o > 0; o >>= 1) acc += __shfl_down_sync(0xffffffffu, acc, o);
    return acc;  // valid on lane 0
}

// ---------------------------------------------------------------------------
// Kernel 0: per-batch small GEMMs -> g_emb, g_avec, g_bvec, g_ce; zero pooled.
// ---------------------------------------------------------------------------
__global__ void k_pre(const float* __restrict__ x, const float* __restrict__ query,
                      const float* __restrict__ Iw, const float* __restrict__ Ib,
                      const float* __restrict__ W1w, const float* __restrict__ W1b,
                      const float* __restrict__ W2w,
                      const float* __restrict__ R1w, const float* __restrict__ R1b,
                      const float* __restrict__ R2w) {
    int b = blockIdx.x, t = threadIdx.x;      // 128 threads, 4 warps
    int lane = t & 31, wid = t >> 5;
    __shared__ float sx[IN_D], sq[Q_D], semb[E], sWi[H], sRq[H], sred[E];
    for (int i = t; i < IN_D; i += 128) sx[i] = x[(size_t)b*IN_D + i];
    for (int i = t; i < Q_D;  i += 128) sq[i] = query[(size_t)b*Q_D + i];
    if (t < E) g_pooled[(size_t)b*E + t] = 0.f;
    __syncthreads();
    for (int o = wid; o < E; o += 4) {
        float d = warp_dot(Iw + (size_t)o*IN_D, sx, IN_D, lane);
        if (lane == 0) { d += Ib[o]; semb[o] = d; g_emb[(size_t)b*E + o] = d; }
    }
    __syncthreads();
    for (int o = wid; o < H; o += 4) {
        float d = warp_dot(W1w + (size_t)o*E, semb, E, lane);
        if (lane == 0) sWi[o] = d + W1b[o];
        float d2 = warp_dot(R1w + (size_t)o*Q_D, sq, Q_D, lane);
        if (lane == 0) sRq[o] = d2 + R1b[o];
    }
    __syncthreads();
    {
        float av = 0.f, bv = 0.f;
        #pragma unroll 8
        for (int h = 0; h < H; h++) {
            av += sWi[h]*W2w[(size_t)h*E + t];
            bv += sRq[h]*R2w[(size_t)h*E + t];
        }
        g_avec[(size_t)b*E + t] = av;
        g_bvec[(size_t)b*E + t] = bv;
        sred[t] = bv*semb[t];
    }
    __syncthreads();
    for (int s = 64; s > 0; s >>= 1) { if (t < s) sred[t] += sred[t+s]; __syncthreads(); }
    if (t == 0) g_ce[b] = sred[0];
}

// ---------------------------------------------------------------------------
// Streaming dots (R8 proven shape, 40 regs): scores = a.mem_row, rbase = b.mem_row.
// ---------------------------------------------------------------------------
__global__ void k_dots(const float* __restrict__ mem) {
    int b = blockIdx.y;
    int warp = threadIdx.x >> 5, lane = threadIdx.x & 31;   // 8 warps
    __shared__ __align__(16) float sa[E];
    __shared__ __align__(16) float sb[E];
    if (threadIdx.x < E) {
        sa[threadIdx.x] = g_avec[(size_t)b*E + threadIdx.x];
        sb[threadIdx.x] = g_bvec[(size_t)b*E + threadIdx.x];
    }
    __syncthreads();
    int m0 = blockIdx.x*32 + warp*4;
    const float4* mrow = (const float4*)(mem + (size_t)b*M*E);
    float4 v[4];
    #pragma unroll
    for (int k = 0; k < 4; k++)
        v[k] = mrow[(size_t)(m0 + k)*32 + lane];
    float4 a  = ((const float4*)sa)[lane];
    float4 bb = ((const float4*)sb)[lane];
    float ds[4], dr[4];
    #pragma unroll
    for (int k = 0; k < 4; k++) {
        ds[k] = v[k].x*a.x + v[k].y*a.y + v[k].z*a.z + v[k].w*a.w;
        dr[k] = v[k].x*bb.x + v[k].y*bb.y + v[k].z*bb.z + v[k].w*bb.w;
    }
    #pragma unroll
    for (int o = 16; o > 0; o >>= 1) {
        #pragma unroll
        for (int k = 0; k < 4; k++) {
            ds[k] += __shfl_down_sync(0xffffffffu, ds[k], o);
            dr[k] += __shfl_down_sync(0xffffffffu, dr[k], o);
        }
    }
    if (lane == 0) {
        #pragma unroll
        for (int k = 0; k < 4; k++) {
            g_scores[(size_t)b*M + m0 + k] = ds[k];
            g_rbase [(size_t)b*M + m0 + k] = dr[k];
        }
    }
}

// ---------------------------------------------------------------------------
// Per-batch fused allocation+softmax (256 thr, 8 elems/thread):
//   usage update -> new_usage
//   EXACT stable argsort via bucket sort: bin = floor(u*256) (monotone in u),
//   shared-atomic histogram, 256-bin prefix sum, scatter, within-bin rank by
//   counting with 64-bit key (float_bits<<11)|index  == jnp.argsort exactly.
//   cumprod scan -> alloc (registers only, never hits global)
//   w = 0.5*(softmax(scores)+alloc) -> NWW;  wr = softmax(rbase + w*ce) -> WR
// ---------------------------------------------------------------------------
typedef cub::BlockScan<unsigned int, 256> ScanU;
typedef cub::BlockScan<float, 256> ScanF;

__global__ void __launch_bounds__(256) k_allocsoft(
        const float* __restrict__ rw, const float* __restrict__ ww,
        const float* __restrict__ us, const float* __restrict__ fg,
        float* __restrict__ out) {
    int b = blockIdx.x, t = threadIdx.x;
    int lane = t & 31, wid = t >> 5;
    size_t base = (size_t)b*M;

    __shared__ union KU {
        unsigned long long       skey[M];   // 16KB (also scan temp space)
        typename ScanU::TempStorage su_t;
        typename ScanF::TempStorage sf_t;
    } smK;
    __shared__ float        ssu[M];         // sorted u, then cumprod in place
    __shared__ unsigned int sstart[257];
    __shared__ unsigned int scur[256];
    __shared__ float sred[8];
    __shared__ float bc;

    // ---- usage update ----
    float u[8];
    {
        float4 U0 = ((const float4*)(us + base))[2*t], U1 = ((const float4*)(us + base))[2*t+1];
        float4 W0 = ((const float4*)(ww + base))[2*t], W1 = ((const float4*)(ww + base))[2*t+1];
        float4 F0 = ((const float4*)(fg + base))[2*t], F1 = ((const float4*)(fg + base))[2*t+1];
        float4 R0 = ((const float4*)(rw + base))[2*t], R1 = ((const float4*)(rw + base))[2*t+1];
        float uu[8] = {U0.x,U0.y,U0.z,U0.w, U1.x,U1.y,U1.z,U1.w};
        float wv[8] = {W0.x,W0.y,W0.z,W0.w, W1.x,W1.y,W1.z,W1.w};
        float ff[8] = {F0.x,F0.y,F0.z,F0.w, F1.x,F1.y,F1.z,F1.w};
        float rr[8] = {R0.x,R0.y,R0.z,R0.w, R1.x,R1.y,R1.z,R1.w};
        #pragma unroll
        for (int j = 0; j < 8; j++) {
            float uv = 1e-5f + (1.f - 1e-5f)*uu[j];
            uv = uv + wv[j] - uv*wv[j];
            uv *= (1.f - ff[j]*rr[j]);
            u[j] = uv;
        }
        ((float4*)(out + OFF_NU + base))[2*t]   = make_float4(u[0],u[1],u[2],u[3]);
        ((float4*)(out + OFF_NU + base))[2*t+1] = make_float4(u[4],u[5],u[6],u[7]);
    }

    // ---- histogram over buckets floor(u*256) ----
    int bkt[8];
    scur[t] = 0;
    __syncthreads();
    #pragma unroll
    for (int j = 0; j < 8; j++) {
        bkt[j] = min(255, max(0, (int)(u[j]*256.f)));
        atomicAdd(&scur[bkt[j]], 1u);
    }
    __syncthreads();

    // ---- bin prefix sum ----
    unsigned int cnt = scur[t], st;
    ScanU(smK.su_t).ExclusiveSum(cnt, st);
    __syncthreads();
    sstart[t] = st;
    if (t == 0) sstart[256] = M;
    scur[t] = st;                 // scatter cursors
    __syncthreads();

    // ---- scatter exact 64-bit keys (stable: low 11 bits = original index) ----
    unsigned long long key[8];
    #pragma unroll
    for (int j = 0; j < 8; j++) {
        key[j] = ((unsigned long long)__float_as_uint(u[j]) << 11) | (unsigned)(8*t + j);
        unsigned int pos = atomicAdd(&scur[bkt[j]], 1u);
        smK.skey[pos] = key[j];
    }
    __syncthreads();

    // ---- rank within bucket (exact, stable) ----
    int p[8];
    #pragma unroll
    for (int j = 0; j < 8; j++) {
        unsigned int s0 = sstart[bkt[j]], s1 = sstart[bkt[j]+1];
        int r = 0;
        for (unsigned int c = s0; c < s1; c++)
            r += (smK.skey[c] < key[j]) ? 1 : 0;
        p[j] = (int)s0 + r;
        ssu[p[j]] = u[j];
    }
    __syncthreads();

    // ---- cumprod over sorted u (in place) ----
    float sv[8], cp[8];
    #pragma unroll
    for (int j = 0; j < 8; j++) sv[j] = ssu[8*t + j];
    __syncthreads();              // all ranking smK reads done before temp reuse
    ScanF(smK.sf_t).InclusiveScan(sv, cp, MulOp());
    __syncthreads();
    #pragma unroll
    for (int j = 0; j < 8; j++) ssu[8*t + j] = cp[j];
    __syncthreads();
    float al[8];
    #pragma unroll
    for (int j = 0; j < 8; j++) al[j] = (1.f - u[j])*ssu[p[j]];

    // ---- softmax(scores); w = 0.5*(softmax + alloc) ----
    float sc[8];
    {
        float4 S0 = ((const float4*)(g_scores + base))[2*t], S1 = ((const float4*)(g_scores + base))[2*t+1];
        sc[0]=S0.x; sc[1]=S0.y; sc[2]=S0.z; sc[3]=S0.w;
        sc[4]=S1.x; sc[5]=S1.y; sc[6]=S1.z; sc[7]=S1.w;
    }
    float v = sc[0];
    #pragma unroll
    for (int j = 1; j < 8; j++) v = fmaxf(v, sc[j]);
    #pragma unroll
    for (int o = 16; o > 0; o >>= 1) v = fmaxf(v, __shfl_xor_sync(0xffffffffu, v, o));
    if (lane == 0) sred[wid] = v;
    __syncthreads();
    if (t < 8) {
        float xx = sred[t];
        #pragma unroll
        for (int o = 4; o > 0; o >>= 1) xx = fmaxf(xx, __shfl_xor_sync(0xffu, xx, o));
        if (t == 0) bc = xx;
    }
    __syncthreads();
    float mx = bc;
    float e[8], sum = 0.f;
    #pragma unroll
    for (int j = 0; j < 8; j++) { e[j] = __expf(sc[j] - mx); sum += e[j]; }
    v = sum;
    #pragma unroll
    for (int o = 16; o > 0; o >>= 1) v += __shfl_xor_sync(0xffffffffu, v, o);
    if (lane == 0) sred[wid] = v;
    __syncthreads();
    if (t < 8) {
        float xx = sred[t];
        #pragma unroll
        for (int o = 4; o > 0; o >>= 1) xx += __shfl_xor_sync(0xffu, xx, o);
        if (t == 0) bc = xx;
    }
    __syncthreads();
    float inv = 1.f/bc;
    float wgt[8];
    #pragma unroll
    for (int j = 0; j < 8; j++) wgt[j] = 0.5f*(e[j]*inv + al[j]);
    ((float4*)(out + OFF_NWW + base))[2*t]   = make_float4(wgt[0],wgt[1],wgt[2],wgt[3]);
    ((float4*)(out + OFF_NWW + base))[2*t+1] = make_float4(wgt[4],wgt[5],wgt[6],wgt[7]);
    __syncthreads();   // bc reuse guard

    // ---- rscores = rbase + w*ce; softmax -> wr ----
    float ce = g_ce[b];
    {
        float4 R0 = ((const float4*)(g_rbase + base))[2*t], R1 = ((const float4*)(g_rbase + base))[2*t+1];
        sc[0]=R0.x; sc[1]=R0.y; sc[2]=R0.z; sc[3]=R0.w;
        sc[4]=R1.x; sc[5]=R1.y; sc[6]=R1.z; sc[7]=R1.w;
    }
    #pragma unroll
    for (int j = 0; j < 8; j++) sc[j] += wgt[j]*ce;
    v = sc[0];
    #pragma unroll
    for (int j = 1; j < 8; j++) v = fmaxf(v, sc[j]);
    #pragma unroll
    for (int o = 16; o > 0; o >>= 1) v = fmaxf(v, __shfl_xor_sync(0xffffffffu, v, o));
    if (lane == 0) sred[wid] = v;
    __syncthreads();
    if (t < 8) {
        float xx = sred[t];
        #pragma unroll
        for (int o = 4; o > 0; o >>= 1) xx = fmaxf(xx, __shfl_xor_sync(0xffu, xx, o));
        if (t == 0) bc = xx;
    }
    __syncthreads();
    mx = bc;
    sum = 0.f;
    #pragma unroll
    for (int j = 0; j < 8; j++) { e[j] = __expf(sc[j] - mx); sum += e[j]; }
    v = sum;
    #pragma unroll
    for (int o = 16; o > 0; o >>= 1) v += __shfl_xor_sync(0xffffffffu, v, o);
    if (lane == 0) sred[wid] = v;
    __syncthreads();
    if (t < 8) {
        float xx = sred[t];
        #pragma unroll
        for (int o = 4; o > 0; o >>= 1) xx += __shfl_xor_sync(0xffu, xx, o);
        if (t == 0) bc = xx;
    }
    __syncthreads();
    inv = 1.f/bc;
    ((float4*)(out + OFF_WR + base))[2*t]   = make_float4(e[0]*inv,e[1]*inv,e[2]*inv,e[3]*inv);
    ((float4*)(out + OFF_WR + base))[2*t+1] = make_float4(e[4]*inv,e[5]*inv,e[6]*inv,e[7]*inv);
}

// ---------------------------------------------------------------------------
// Pass B: new_mem = mem + w*emb (write), pooled += wr*new_mem.
// Reverse batch order: tail of `mem` is still L2-resident from k_dots.
// ---------------------------------------------------------------------------
__global__ void k_passB(const float* __restrict__ mem, float* __restrict__ out) {
    int b = B - 1 - blockIdx.y;
    int warp = threadIdx.x >> 5, lane = threadIdx.x & 31;
    __shared__ __align__(16) float semb[E];
    __shared__ float spool[E];
    if (threadIdx.x < E) {
        semb[threadIdx.x] = g_emb[(size_t)b*E + threadIdx.x];
        spool[threadIdx.x] = 0.f;
    }
    __syncthreads();
    float4 em = ((const float4*)semb)[lane];
    const float* wptr  = out + OFF_NWW + (size_t)b*M;
    const float* wrptr = out + OFF_WR  + (size_t)b*M;
    float4 p = make_float4(0.f, 0.f, 0.f, 0.f);
    int mbase = blockIdx.x*128 + warp*16;
    #pragma unroll 4
    for (int r = 0; r < 16; r++) {
        int m = mbase + r;
        float wv  = wptr[m];
        float wrv = wrptr[m];
        const float4* row = (const float4*)(mem + ((size_t)b*M + m)*E);
        float4 v = row[lane];
        float4 nm;
        nm.x = v.x + wv*em.x; nm.y = v.y + wv*em.y;
        nm.z = v.z + wv*em.z; nm.w = v.w + wv*em.w;
        ((float4*)(out + OFF_NM + ((size_t)b*M + m)*E))[lane] = nm;
        p.x += wrv*nm.x; p.y += wrv*nm.y; p.z += wrv*nm.z; p.w += wrv*nm.w;
    }
    atomicAdd(&spool[lane*4+0], p.x);
    atomicAdd(&spool[lane*4+1], p.y);
    atomicAdd(&spool[lane*4+2], p.z);
    atomicAdd(&spool[lane*4+3], p.w);
    __syncthreads();
    if (threadIdx.x < E)
        atomicAdd(&g_pooled[(size_t)b*E + threadIdx.x], spool[threadIdx.x]);
}

// ---------------------------------------------------------------------------
// Output projection: grid (8, B), warp per output row, 8 rows per warp.
// ---------------------------------------------------------------------------
__global__ void k_out(const float* __restrict__ Ow, const float* __restrict__ Ob,
                      float* __restrict__ out) {
    int b = blockIdx.y, chunk = blockIdx.x;
    int lane = threadIdx.x & 31, wid = threadIdx.x >> 5;   // 8 warps
    __shared__ __align__(16) float sp[E];
    if (threadIdx.x < E) sp[threadIdx.x] = g_pooled[(size_t)b*E + threadIdx.x];
    __syncthreads();
    float4 pv = ((const float4*)sp)[lane];
    int o0 = chunk*64 + wid*8;
    float d[8];
    #pragma unroll
    for (int r = 0; r < 8; r++) {
        float4 wv = ((const float4*)(Ow + (size_t)(o0 + r)*E))[lane];
        d[r] = wv.x*pv.x + wv.y*pv.y + wv.z*pv.z + wv.w*pv.w;
    }
    #pragma unroll
    for (int o = 16; o > 0; o >>= 1) {
        #pragma unroll
        for (int r = 0; r < 8; r++)
            d[r] += __shfl_down_sync(0xffffffffu, d[r], o);
    }
    if (lane == 0) {
        #pragma unroll
        for (int r = 0; r < 8; r++)
            out[OFF_OUT + (size_t)b*OUT_D + o0 + r] = d[r] + Ob[o0 + r];
    }
}

extern "C" void kernel_launch(void* const* d_in, const int* in_sizes, int n_in,
                              void* d_out, int out_size) {
    const float* rw  = (const float*)d_in[0];
    const float* ww  = (const float*)d_in[1];
    const float* us  = (const float*)d_in[2];
    const float* fg  = (const float*)d_in[3];
    const float* x   = (const float*)d_in[4];
    const float* q   = (const float*)d_in[5];
    const float* mem = (const float*)d_in[6];
    const float* Iw  = (const float*)d_in[7];
    const float* Ib  = (const float*)d_in[8];
    const float* W1w = (const float*)d_in[9];
    const float* W1b = (const float*)d_in[10];
    const float* W2w = (const float*)d_in[11];
    // d_in[12] = W2_b: per-batch constant, cancels in softmax
    const float* R1w = (const float*)d_in[13];
    const float* R1b = (const float*)d_in[14];
    const float* R2w = (const float*)d_in[15];
    // d_in[16] = R2_b: per-batch constant, cancels in softmax
    const float* Ow  = (const float*)d_in[17];
    const float* Ob  = (const float*)d_in[18];
    float* out = (float*)d_out;

    k_pre      <<<B, 128>>>(x, q, Iw, Ib, W1w, W1b, W2w, R1w, R1b, R2w);
    k_dots     <<<dim3(M/32, B), 256>>>(mem);
    k_allocsoft<<<B, 256>>>(rw, ww, us, fg, out);
    k_passB    <<<dim3(M/128, B), 256>>>(mem, out);
    k_out      <<<dim3(8, B), 256>>>(Ow, Ob, out);
}

// round 14
// speedup vs baseline: 1.0277x; 1.0015x over previous
#include <cuda_runtime.h>
#include <cub/cub.cuh>

#define B 256
#define M 2048
#define E 128
#define IN_D 512
#define Q_D 512
#define OUT_D 512
#define H 64

// output layout (depth-first flatten of ((wr, nww, nu), output, new_memory))
#define OFF_WR  ((size_t)0)
#define OFF_NWW ((size_t)B*M)
#define OFF_NU  ((size_t)2*B*M)
#define OFF_OUT ((size_t)3*B*M)
#define OFF_NM  ((size_t)3*B*M + (size_t)B*OUT_D)

// scratch (device globals: no allocation allowed)
__device__ float g_emb[B*E];
__device__ float g_avec[B*E];
__device__ float g_bvec[B*E];
__device__ float g_ce[B];
__device__ float g_scores[B*M];
__device__ float g_rbase[B*M];
__device__ float g_pooled[B*E];

struct MulOp {
    __device__ __forceinline__ float operator()(const float& a, const float& b) const { return a*b; }
};

__device__ __forceinline__ float warp_dot(const float* __restrict__ w,
                                          const float* __restrict__ s,
                                          int n, int lane) {
    float acc = 0.f;
    for (int i = lane; i < n; i += 32) acc += w[i]*s[i];
    #pragma unroll
    for (int o = 16; o > 0; o >>= 1) acc += __shfl_down_sync(0xffffffffu, acc, o);
    return acc;  // valid on lane 0
}

// ---------------------------------------------------------------------------
// Kernel 0: per-batch small GEMMs -> g_emb, g_avec, g_bvec, g_ce; zero pooled.
// ---------------------------------------------------------------------------
__global__ void k_pre(const float* __restrict__ x, const float* __restrict__ query,
                      const float* __restrict__ Iw, const float* __restrict__ Ib,
                      const float* __restrict__ W1w, const float* __restrict__ W1b,
                      const float* __restrict__ W2w,
                      const float* __restrict__ R1w, const float* __restrict__ R1b,
                      const float* __restrict__ R2w) {
    int b = blockIdx.x, t = threadIdx.x;      // 128 threads, 4 warps
    int lane = t & 31, wid = t >> 5;
    __shared__ float sx[IN_D], sq[Q_D], semb[E], sWi[H], sRq[H], sred[E];
    for (int i = t; i < IN_D; i += 128) sx[i] = x[(size_t)b*IN_D + i];
    for (int i = t; i < Q_D;  i += 128) sq[i] = query[(size_t)b*Q_D + i];
    if (t < E) g_pooled[(size_t)b*E + t] = 0.f;
    __syncthreads();
    for (int o = wid; o < E; o += 4) {
        float d = warp_dot(Iw + (size_t)o*IN_D, sx, IN_D, lane);
        if (lane == 0) { d += Ib[o]; semb[o] = d; g_emb[(size_t)b*E + o] = d; }
    }
    __syncthreads();
    for (int o = wid; o < H; o += 4) {
        float d = warp_dot(W1w + (size_t)o*E, semb, E, lane);
        if (lane == 0) sWi[o] = d + W1b[o];
        float d2 = warp_dot(R1w + (size_t)o*Q_D, sq, Q_D, lane);
        if (lane == 0) sRq[o] = d2 + R1b[o];
    }
    __syncthreads();
    {
        float av = 0.f, bv = 0.f;
        #pragma unroll 8
        for (int h = 0; h < H; h++) {
            av += sWi[h]*W2w[(size_t)h*E + t];
            bv += sRq[h]*R2w[(size_t)h*E + t];
        }
        g_avec[(size_t)b*E + t] = av;
        g_bvec[(size_t)b*E + t] = bv;
        sred[t] = bv*semb[t];
    }
    __syncthreads();
    for (int s = 64; s > 0; s >>= 1) { if (t < s) sred[t] += sred[t+s]; __syncthreads(); }
    if (t == 0) g_ce[b] = sred[0];
}

// ---------------------------------------------------------------------------
// Streaming dots, passB-shaped: grid (M/128, B), 256 thr, warp owns 16 rows
// in 4 independent groups of 4 (MLP=4 per group, groups pipeline). Header
// (sa/sb) amortized over 128 rows per block.
//   scores = a_vec . mem_row,  rbase = b_vec . mem_row
// ---------------------------------------------------------------------------
__global__ void k_dots(const float* __restrict__ mem) {
    int b = blockIdx.y;
    int warp = threadIdx.x >> 5, lane = threadIdx.x & 31;   // 8 warps
    __shared__ __align__(16) float sa[E];
    __shared__ __align__(16) float sb[E];
    if (threadIdx.x < E) {
        sa[threadIdx.x] = g_avec[(size_t)b*E + threadIdx.x];
        sb[threadIdx.x] = g_bvec[(size_t)b*E + threadIdx.x];
    }
    __syncthreads();
    float4 a  = ((const float4*)sa)[lane];
    float4 bb = ((const float4*)sb)[lane];
    const float4* mrow = (const float4*)(mem + (size_t)b*M*E);
    int mbase = blockIdx.x*128 + warp*16;
    #pragma unroll
    for (int g = 0; g < 4; g++) {
        int m0 = mbase + g*4;
        float4 v[4];
        #pragma unroll
        for (int k = 0; k < 4; k++)
            v[k] = mrow[(size_t)(m0 + k)*32 + lane];
        float ds[4], dr[4];
        #pragma unroll
        for (int k = 0; k < 4; k++) {
            ds[k] = v[k].x*a.x + v[k].y*a.y + v[k].z*a.z + v[k].w*a.w;
            dr[k] = v[k].x*bb.x + v[k].y*bb.y + v[k].z*bb.z + v[k].w*bb.w;
        }
        #pragma unroll
        for (int o = 16; o > 0; o >>= 1) {
            #pragma unroll
            for (int k = 0; k < 4; k++) {
                ds[k] += __shfl_down_sync(0xffffffffu, ds[k], o);
                dr[k] += __shfl_down_sync(0xffffffffu, dr[k], o);
            }
        }
        if (lane == 0) {
            #pragma unroll
            for (int k = 0; k < 4; k++) {
                g_scores[(size_t)b*M + m0 + k] = ds[k];
                g_rbase [(size_t)b*M + m0 + k] = dr[k];
            }
        }
    }
}

// ---------------------------------------------------------------------------
// Per-batch fused allocation+softmax (256 thr, 8 elems/thread):
//   usage update -> new_usage
//   EXACT stable argsort via bucket sort: bin = floor(u*256) (monotone in u),
//   shared-atomic histogram, 256-bin prefix sum, scatter, within-bin rank by
//   counting with 64-bit key (float_bits<<11)|index  == jnp.argsort exactly.
//   cumprod scan -> alloc; w = 0.5*(softmax(scores)+alloc) -> NWW;
//   wr = softmax(rbase + w*ce) -> WR
// ---------------------------------------------------------------------------
typedef cub::BlockScan<unsigned int, 256> ScanU;
typedef cub::BlockScan<float, 256> ScanF;

__global__ void __launch_bounds__(256) k_allocsoft(
        const float* __restrict__ rw, const float* __restrict__ ww,
        const float* __restrict__ us, const float* __restrict__ fg,
        float* __restrict__ out) {
    int b = blockIdx.x, t = threadIdx.x;
    int lane = t & 31, wid = t >> 5;
    size_t base = (size_t)b*M;

    __shared__ union KU {
        unsigned long long       skey[M];   // 16KB (also scan temp space)
        typename ScanU::TempStorage su_t;
        typename ScanF::TempStorage sf_t;
    } smK;
    __shared__ float        ssu[M];         // sorted u, then cumprod in place
    __shared__ unsigned int sstart[257];
    __shared__ unsigned int scur[256];
    __shared__ float sred[8];
    __shared__ float bc;

    // ---- usage update ----
    float u[8];
    {
        float4 U0 = ((const float4*)(us + base))[2*t], U1 = ((const float4*)(us + base))[2*t+1];
        float4 W0 = ((const float4*)(ww + base))[2*t], W1 = ((const float4*)(ww + base))[2*t+1];
        float4 F0 = ((const float4*)(fg + base))[2*t], F1 = ((const float4*)(fg + base))[2*t+1];
        float4 R0 = ((const float4*)(rw + base))[2*t], R1 = ((const float4*)(rw + base))[2*t+1];
        float uu[8] = {U0.x,U0.y,U0.z,U0.w, U1.x,U1.y,U1.z,U1.w};
        float wv[8] = {W0.x,W0.y,W0.z,W0.w, W1.x,W1.y,W1.z,W1.w};
        float ff[8] = {F0.x,F0.y,F0.z,F0.w, F1.x,F1.y,F1.z,F1.w};
        float rr[8] = {R0.x,R0.y,R0.z,R0.w, R1.x,R1.y,R1.z,R1.w};
        #pragma unroll
        for (int j = 0; j < 8; j++) {
            float uv = 1e-5f + (1.f - 1e-5f)*uu[j];
            uv = uv + wv[j] - uv*wv[j];
            uv *= (1.f - ff[j]*rr[j]);
            u[j] = uv;
        }
        ((float4*)(out + OFF_NU + base))[2*t]   = make_float4(u[0],u[1],u[2],u[3]);
        ((float4*)(out + OFF_NU + base))[2*t+1] = make_float4(u[4],u[5],u[6],u[7]);
    }

    // ---- histogram over buckets floor(u*256) ----
    int bkt[8];
    scur[t] = 0;
    __syncthreads();
    #pragma unroll
    for (int j = 0; j < 8; j++) {
        bkt[j] = min(255, max(0, (int)(u[j]*256.f)));
        atomicAdd(&scur[bkt[j]], 1u);
    }
    __syncthreads();

    // ---- bin prefix sum ----
    unsigned int cnt = scur[t], st;
    ScanU(smK.su_t).ExclusiveSum(cnt, st);
    __syncthreads();
    sstart[t] = st;
    if (t == 0) sstart[256] = M;
    scur[t] = st;                 // scatter cursors
    __syncthreads();

    // ---- scatter exact 64-bit keys (stable: low 11 bits = original index) ----
    unsigned long long key[8];
    #pragma unroll
    for (int j = 0; j < 8; j++) {
        key[j] = ((unsigned long long)__float_as_uint(u[j]) << 11) | (unsigned)(8*t + j);
        unsigned int pos = atomicAdd(&scur[bkt[j]], 1u);
        smK.skey[pos] = key[j];
    }
    __syncthreads();

    // ---- rank within bucket (exact, stable) ----
    int p[8];
    #pragma unroll
    for (int j = 0; j < 8; j++) {
        unsigned int s0 = sstart[bkt[j]], s1 = sstart[bkt[j]+1];
        int r = 0;
        for (unsigned int c = s0; c < s1; c++)
            r += (smK.skey[c] < key[j]) ? 1 : 0;
        p[j] = (int)s0 + r;
        ssu[p[j]] = u[j];
    }
    __syncthreads();

    // ---- cumprod over sorted u (in place) ----
    float sv[8], cp[8];
    #pragma unroll
    for (int j = 0; j < 8; j++) sv[j] = ssu[8*t + j];
    __syncthreads();              // all ranking smK reads done before temp reuse
    ScanF(smK.sf_t).InclusiveScan(sv, cp, MulOp());
    __syncthreads();
    #pragma unroll
    for (int j = 0; j < 8; j++) ssu[8*t + j] = cp[j];
    __syncthreads();
    float al[8];
    #pragma unroll
    for (int j = 0; j < 8; j++) al[j] = (1.f - u[j])*ssu[p[j]];

    // ---- softmax(scores); w = 0.5*(softmax + alloc) ----
    float sc[8];
    {
        float4 S0 = ((const float4*)(g_scores + base))[2*t], S1 = ((const float4*)(g_scores + base))[2*t+1];
        sc[0]=S0.x; sc[1]=S0.y; sc[2]=S0.z; sc[3]=S0.w;
        sc[4]=S1.x; sc[5]=S1.y; sc[6]=S1.z; sc[7]=S1.w;
    }
    float v = sc[0];
    #pragma unroll
    for (int j = 1; j < 8; j++) v = fmaxf(v, sc[j]);
    #pragma unroll
    for (int o = 16; o > 0; o >>= 1) v = fmaxf(v, __shfl_xor_sync(0xffffffffu, v, o));
    if (lane == 0) sred[wid] = v;
    __syncthreads();
    if (t < 8) {
        float xx = sred[t];
        #pragma unroll
        for (int o = 4; o > 0; o >>= 1) xx = fmaxf(xx, __shfl_xor_sync(0xffu, xx, o));
        if (t == 0) bc = xx;
    }
    __syncthreads();
    float mx = bc;
    float e[8], sum = 0.f;
    #pragma unroll
    for (int j = 0; j < 8; j++) { e[j] = __expf(sc[j] - mx); sum += e[j]; }
    v = sum;
    #pragma unroll
    for (int o = 16; o > 0; o >>= 1) v += __shfl_xor_sync(0xffffffffu, v, o);
    if (lane == 0) sred[wid] = v;
    __syncthreads();
    if (t < 8) {
        float xx = sred[t];
        #pragma unroll
        for (int o = 4; o > 0; o >>= 1) xx += __shfl_xor_sync(0xffu, xx, o);
        if (t == 0) bc = xx;
    }
    __syncthreads();
    float inv = 1.f/bc;
    float wgt[8];
    #pragma unroll
    for (int j = 0; j < 8; j++) wgt[j] = 0.5f*(e[j]*inv + al[j]);
    ((float4*)(out + OFF_NWW + base))[2*t]   = make_float4(wgt[0],wgt[1],wgt[2],wgt[3]);
    ((float4*)(out + OFF_NWW + base))[2*t+1] = make_float4(wgt[4],wgt[5],wgt[6],wgt[7]);
    __syncthreads();   // bc reuse guard

    // ---- rscores = rbase + w*ce; softmax -> wr ----
    float ce = g_ce[b];
    {
        float4 R0 = ((const float4*)(g_rbase + base))[2*t], R1 = ((const float4*)(g_rbase + base))[2*t+1];
        sc[0]=R0.x; sc[1]=R0.y; sc[2]=R0.z; sc[3]=R0.w;
        sc[4]=R1.x; sc[5]=R1.y; sc[6]=R1.z; sc[7]=R1.w;
    }
    #pragma unroll
    for (int j = 0; j < 8; j++) sc[j] += wgt[j]*ce;
    v = sc[0];
    #pragma unroll
    for (int j = 1; j < 8; j++) v = fmaxf(v, sc[j]);
    #pragma unroll
    for (int o = 16; o > 0; o >>= 1) v = fmaxf(v, __shfl_xor_sync(0xffffffffu, v, o));
    if (lane == 0) sred[wid] = v;
    __syncthreads();
    if (t < 8) {
        float xx = sred[t];
        #pragma unroll
        for (int o = 4; o > 0; o >>= 1) xx = fmaxf(xx, __shfl_xor_sync(0xffu, xx, o));
        if (t == 0) bc = xx;
    }
    __syncthreads();
    mx = bc;
    sum = 0.f;
    #pragma unroll
    for (int j = 0; j < 8; j++) { e[j] = __expf(sc[j] - mx); sum += e[j]; }
    v = sum;
    #pragma unroll
    for (int o = 16; o > 0; o >>= 1) v += __shfl_xor_sync(0xffffffffu, v, o);
    if (lane == 0) sred[wid] = v;
    __syncthreads();
    if (t < 8) {
        float xx = sred[t];
        #pragma unroll
        for (int o = 4; o > 0; o >>= 1) xx += __shfl_xor_sync(0xffu, xx, o);
        if (t == 0) bc = xx;
    }
    __syncthreads();
    inv = 1.f/bc;
    ((float4*)(out + OFF_WR + base))[2*t]   = make_float4(e[0]*inv,e[1]*inv,e[2]*inv,e[3]*inv);
    ((float4*)(out + OFF_WR + base))[2*t+1] = make_float4(e[4]*inv,e[5]*inv,e[6]*inv,e[7]*inv);
}

// ---------------------------------------------------------------------------
// Pass B: new_mem = mem + w*emb (write), pooled += wr*new_mem.
// Reverse batch order: tail of `mem` is still L2-resident from k_dots.
// ---------------------------------------------------------------------------
__global__ void k_passB(const float* __restrict__ mem, float* __restrict__ out) {
    int b = B - 1 - blockIdx.y;
    int warp = threadIdx.x >> 5, lane = threadIdx.x & 31;
    __shared__ __align__(16) float semb[E];
    __shared__ float spool[E];
    if (threadIdx.x < E) {
        semb[threadIdx.x] = g_emb[(size_t)b*E + threadIdx.x];
        spool[threadIdx.x] = 0.f;
    }
    __syncthreads();
    float4 em = ((const float4*)semb)[lane];
    const float* wptr  = out + OFF_NWW + (size_t)b*M;
    const float* wrptr = out + OFF_WR  + (size_t)b*M;
    float4 p = make_float4(0.f, 0.f, 0.f, 0.f);
    int mbase = blockIdx.x*128 + warp*16;
    #pragma unroll 4
    for (int r = 0; r < 16; r++) {
        int m = mbase + r;
        float wv  = wptr[m];
        float wrv = wrptr[m];
        const float4* row = (const float4*)(mem + ((size_t)b*M + m)*E);
        float4 v = row[lane];
        float4 nm;
        nm.x = v.x + wv*em.x; nm.y = v.y + wv*em.y;
        nm.z = v.z + wv*em.z; nm.w = v.w + wv*em.w;
        ((float4*)(out + OFF_NM + ((size_t)b*M + m)*E))[lane] = nm;
        p.x += wrv*nm.x; p.y += wrv*nm.y; p.z += wrv*nm.z; p.w += wrv*nm.w;
    }
    atomicAdd(&spool[lane*4+0], p.x);
    atomicAdd(&spool[lane*4+1], p.y);
    atomicAdd(&spool[lane*4+2], p.z);
    atomicAdd(&spool[lane*4+3], p.w);
    __syncthreads();
    if (threadIdx.x < E)
        atomicAdd(&g_pooled[(size_t)b*E + threadIdx.x], spool[threadIdx.x]);
}

// ---------------------------------------------------------------------------
// Output projection: grid (8, B), warp per output row, 8 rows per warp.
// ---------------------------------------------------------------------------
__global__ void k_out(const float* __restrict__ Ow, const float* __restrict__ Ob,
                      float* __restrict__ out) {
    int b = blockIdx.y, chunk = blockIdx.x;
    int lane = threadIdx.x & 31, wid = threadIdx.x >> 5;   // 8 warps
    __shared__ __align__(16) float sp[E];
    if (threadIdx.x < E) sp[threadIdx.x] = g_pooled[(size_t)b*E + threadIdx.x];
    __syncthreads();
    float4 pv = ((const float4*)sp)[lane];
    int o0 = chunk*64 + wid*8;
    float d[8];
    #pragma unroll
    for (int r = 0; r < 8; r++) {
        float4 wv = ((const float4*)(Ow + (size_t)(o0 + r)*E))[lane];
        d[r] = wv.x*pv.x + wv.y*pv.y + wv.z*pv.z + wv.w*pv.w;
    }
    #pragma unroll
    for (int o = 16; o > 0; o >>= 1) {
        #pragma unroll
        for (int r = 0; r < 8; r++)
            d[r] += __shfl_down_sync(0xffffffffu, d[r], o);
    }
    if (lane == 0) {
        #pragma unroll
        for (int r = 0; r < 8; r++)
            out[OFF_OUT + (size_t)b*OUT_D + o0 + r] = d[r] + Ob[o0 + r];
    }
}

extern "C" void kernel_launch(void* const* d_in, const int* in_sizes, int n_in,
                              void* d_out, int out_size) {
    const float* rw  = (const float*)d_in[0];
    const float* ww  = (const float*)d_in[1];
    const float* us  = (const float*)d_in[2];
    const float* fg  = (const float*)d_in[3];
    const float* x   = (const float*)d_in[4];
    const float* q   = (const float*)d_in[5];
    const float* mem = (const float*)d_in[6];
    const float* Iw  = (const float*)d_in[7];
    const float* Ib  = (const float*)d_in[8];
    const float* W1w = (const float*)d_in[9];
    const float* W1b = (const float*)d_in[10];
    const float* W2w = (const float*)d_in[11];
    // d_in[12] = W2_b: per-batch constant, cancels in softmax
    const float* R1w = (const float*)d_in[13];
    const float* R1b = (const float*)d_in[14];
    const float* R2w = (const float*)d_in[15];
    // d_in[16] = R2_b: per-batch constant, cancels in softmax
    const float* Ow  = (const float*)d_in[17];
    const float* Ob  = (const float*)d_in[18];
    float* out = (float*)d_out;

    k_pre      <<<B, 128>>>(x, q, Iw, Ib, W1w, W1b, W2w, R1w, R1b, R2w);
    k_dots     <<<dim3(M/128, B), 256>>>(mem);
    k_allocsoft<<<B, 256>>>(rw, ww, us, fg, out);
    k_passB    <<<dim3(M/128, B), 256>>>(mem, out);
    k_out      <<<dim3(8, B), 256>>>(Ow, Ob, out);
}